// round 7
// baseline (speedup 1.0000x reference)
#include <cuda_runtime.h>

// Fixed problem shape
#define NPIX      102400            // B*H*W = 4*160*160
#define HW        25600             // H*W
#define NV        1024
#define OUT_ELEMS (NV * 2 * 32 * 32)   // 2,097,152 floats = 524,288 float4

// Gaussian in bin coordinates: t = (x+1)*16 - 0.5, sigma_bins = 0.8
// log2-space coefficient: -0.5/(0.8^2) * log2(e)
#define CEXP   (-1.12710546f)
#define SKIPTH (2e-5f)

__device__ int g_sizes[NV];

// ---------------------------------------------------------------------------
// Kernel 1: zero output + g_sizes.
// 1024 blocks x 256 threads x 2 float4 = 524,288 float4 = OUT_ELEMS exactly.
// ---------------------------------------------------------------------------
__global__ void zero_kernel(float4* __restrict__ out) {
    int t4 = blockIdx.x * 512 + threadIdx.x;
    float4 z = make_float4(0.f, 0.f, 0.f, 0.f);
    out[t4]       = z;
    out[t4 + 256] = z;
    int i = blockIdx.x * blockDim.x + threadIdx.x;
    if (i < NV) g_sizes[i] = 0;
}

// ---------------------------------------------------------------------------
// Kernel 2: segment bincount (after zero kernel -> ordered, no race)
// ---------------------------------------------------------------------------
__global__ void count_kernel(const int* __restrict__ seg) {
    int n = blockIdx.x * blockDim.x + threadIdx.x;
    if (n < NPIX) atomicAdd(&g_sizes[seg[n]], 1);
}

// ---------------------------------------------------------------------------
// Predicated vector reduction: issue red.v4 only if gate > SKIPTH.
// ---------------------------------------------------------------------------
__device__ __forceinline__ void red4p(float gate, float* p,
                                      float a, float b, float c, float d) {
    asm volatile(
        "{\n\t"
        ".reg .pred pg;\n\t"
        "setp.gt.f32 pg, %0, %1;\n\t"
        "@pg red.global.add.v4.f32 [%2], {%3,%4,%5,%6};\n\t"
        "}"
        :: "f"(gate), "f"(SKIPTH), "l"(p), "f"(a), "f"(b), "f"(c), "f"(d)
        : "memory");
}

// ---------------------------------------------------------------------------
// Kernel 3: windowed Parzen scatter, per-pixel, normalization folded in.
// p-window: 6 bins (floor-2..floor+3), q-window: 12 bins 4-aligned,
// chunks with product weight < 2e-5 predicated off (support radius ~3.7 bins).
// Bound by per-SM REDG lane rate -> minimize red.v4 instruction count.
// ---------------------------------------------------------------------------
__global__ void __launch_bounds__(256)
hist_kernel(const int* __restrict__ seg,
            const int* __restrict__ byx,
            const float* __restrict__ grad,
            float* __restrict__ out) {
    int n = blockIdx.x * blockDim.x + threadIdx.x;
    if (n >= NPIX) return;

    int v = seg[n];
    float inv = 1.0f / (float)__ldg(&g_sizes[v]);   // den = sizes * (P/32)^2 = sizes

    // bin coordinates: t = (x+1)*16 - 0.5
    float t0 = (float)byx[NPIX + n]     * 0.2f - 0.5f;
    float t1 = (float)byx[2 * NPIX + n] * 0.2f - 0.5f;
    int   b  = n / HW;
    int   hw = n - b * HW;
    float t2 = grad[b * 2 * HW + hw]      * 16.f + 15.5f;
    float t3 = grad[b * 2 * HW + HW + hw] * 16.f + 15.5f;

    float* base0 = out + (size_t)v * 2048;

    // ---- pair 0: dims (0,1) — always in range ----
    {
        int lo0 = min(26, max(0, __float2int_rd(t0) - 2));
        float w0[6];
#pragma unroll
        for (int k = 0; k < 6; k++) {
            float d = t0 - (float)(lo0 + k);
            w0[k] = exp2f(CEXP * d * d);
        }
        int qa1 = min(20, max(0, (__float2int_rd(t1) - 3) & ~3));
        float w1[12];
#pragma unroll
        for (int k = 0; k < 12; k++) {
            float d = t1 - (float)(qa1 + k);
            w1[k] = exp2f(CEXP * d * d);
        }
        float m0 = fmaxf(fmaxf(w1[0], w1[1]),  fmaxf(w1[2],  w1[3]));
        float m1 = fmaxf(fmaxf(w1[4], w1[5]),  fmaxf(w1[6],  w1[7]));
        float m2 = fmaxf(fmaxf(w1[8], w1[9]),  fmaxf(w1[10], w1[11]));
#pragma unroll
        for (int p = 0; p < 6; p++) {
            float wr = w0[p];
            float a  = wr * inv;
            float* row = base0 + (lo0 + p) * 32 + qa1;
            red4p(wr * m0, row,     a * w1[0], a * w1[1], a * w1[2],  a * w1[3]);
            red4p(wr * m1, row + 4, a * w1[4], a * w1[5], a * w1[6],  a * w1[7]);
            red4p(wr * m2, row + 8, a * w1[8], a * w1[9], a * w1[10], a * w1[11]);
        }
    }

    // ---- pair 1: dims (2,3) — grads can fall outside all bins -> skip ----
    if (t2 > -3.5f && t2 < 34.5f && t3 > -3.5f && t3 < 34.5f) {
        int lo2 = min(26, max(0, __float2int_rd(t2) - 2));
        float w2[6];
#pragma unroll
        for (int k = 0; k < 6; k++) {
            float d = t2 - (float)(lo2 + k);
            w2[k] = exp2f(CEXP * d * d);
        }
        int qa3 = min(20, max(0, (__float2int_rd(t3) - 3) & ~3));
        float w3[12];
#pragma unroll
        for (int k = 0; k < 12; k++) {
            float d = t3 - (float)(qa3 + k);
            w3[k] = exp2f(CEXP * d * d);
        }
        float m0 = fmaxf(fmaxf(w3[0], w3[1]),  fmaxf(w3[2],  w3[3]));
        float m1 = fmaxf(fmaxf(w3[4], w3[5]),  fmaxf(w3[6],  w3[7]));
        float m2 = fmaxf(fmaxf(w3[8], w3[9]),  fmaxf(w3[10], w3[11]));
        float* base1 = base0 + 1024;
#pragma unroll
        for (int p = 0; p < 6; p++) {
            float wr = w2[p];
            float a  = wr * inv;
            float* row = base1 + (lo2 + p) * 32 + qa3;
            red4p(wr * m0, row,     a * w3[0], a * w3[1], a * w3[2],  a * w3[3]);
            red4p(wr * m1, row + 4, a * w3[4], a * w3[5], a * w3[6],  a * w3[7]);
            red4p(wr * m2, row + 8, a * w3[8], a * w3[9], a * w3[10], a * w3[11]);
        }
    }
}

// ---------------------------------------------------------------------------
extern "C" void kernel_launch(void* const* d_in, const int* in_sizes, int n_in,
                              void* d_out, int out_size) {
    const int*   seg  = (const int*)d_in[0];
    const int*   byx  = (const int*)d_in[1];
    const float* grad = (const float*)d_in[2];
    float*       out  = (float*)d_out;

    zero_kernel<<<1024, 256>>>((float4*)out);
    count_kernel<<<(NPIX + 255) / 256, 256>>>(seg);
    hist_kernel<<<(NPIX + 255) / 256, 256>>>(seg, byx, grad, out);
}